// round 16
// baseline (speedup 1.0000x reference)
#include <cuda_runtime.h>
#include <cuda_bf16.h>
#include <cstdint>

#define NN 32768
#define SWZ(o) ((o) ^ (((o) >> 3) & 0x70))

__device__ __align__(128) __nv_bfloat16 g_xh[(size_t)2 * NN * 256];
__device__ __align__(128) __nv_bfloat16 g_xl[(size_t)2 * NN * 256];
__device__ __align__(128) __nv_bfloat16 g_B1b[768u * 768];
__device__ __align__(128) float g_bias1[768];
__device__ __align__(128) __nv_bfloat16 g_swh[(size_t)2 * NN * 512];
__device__ __align__(128) __nv_bfloat16 g_swl[(size_t)2 * NN * 512];
__device__ __align__(128) __nv_bfloat16 g_fxh[(size_t)2 * NN * 256];
__device__ __align__(128) __nv_bfloat16 g_fxl[(size_t)2 * NN * 256];
__device__ __align__(128) float g_num[2 * 8 * 64 * 32];
__device__ __align__(128) float g_den[2 * 8 * 64];
__device__ __align__(128) __nv_bfloat16 g_Mb[(size_t)2 * 256 * 1536];

__device__ __forceinline__ uint32_t s2u(const void* p) {
    uint32_t a;
    asm("{ .reg .u64 t; cvta.to.shared.u64 t, %1; cvt.u32.u64 %0, t; }" : "=r"(a) : "l"(p));
    return a;
}
__device__ __forceinline__ void cpa16(uint32_t dst, const void* src) {
    asm volatile("cp.async.cg.shared.global [%0], [%1], 16;" :: "r"(dst), "l"(src));
}
__device__ __forceinline__ void cpa_commit() { asm volatile("cp.async.commit_group;" ::: "memory"); }
template <int N>
__device__ __forceinline__ void cpa_wait() { asm volatile("cp.async.wait_group %0;" :: "n"(N) : "memory"); }

__device__ __forceinline__ void ldsm4(uint32_t* r, uint32_t addr) {
    asm volatile("ldmatrix.sync.aligned.m8n8.x4.shared.b16 {%0,%1,%2,%3}, [%4];"
                 : "=r"(r[0]), "=r"(r[1]), "=r"(r[2]), "=r"(r[3]) : "r"(addr));
}
__device__ __forceinline__ void ldsm4t(uint32_t* r, uint32_t addr) {
    asm volatile("ldmatrix.sync.aligned.m8n8.x4.trans.shared.b16 {%0,%1,%2,%3}, [%4];"
                 : "=r"(r[0]), "=r"(r[1]), "=r"(r[2]), "=r"(r[3]) : "r"(addr));
}
__device__ __forceinline__ void mma_bf16(float* c, const uint32_t* a, uint32_t b0, uint32_t b1) {
    asm volatile("mma.sync.aligned.m16n8k16.row.col.f32.bf16.bf16.f32 "
                 "{%0,%1,%2,%3},{%4,%5,%6,%7},{%8,%9},{%0,%1,%2,%3};"
                 : "+f"(c[0]), "+f"(c[1]), "+f"(c[2]), "+f"(c[3])
                 : "r"(a[0]), "r"(a[1]), "r"(a[2]), "r"(a[3]), "r"(b0), "r"(b1));
}

// one 64-k chunk: warp (wm 0..3, wn 0..1) computes 32x64 of the 128x128 tile
__device__ __forceinline__ void compute_chunk(uint32_t abase, uint32_t bbase, int wm, int wn,
                                              int lane, float (&acc)[2][8][4]) {
    const int l15 = lane & 15, l16 = (lane >> 4) << 4;
    uint32_t arb[2], brb[4];
    int asz[2], bsz[4];
    #pragma unroll
    for (int mf = 0; mf < 2; ++mf) {
        int r = wm * 32 + mf * 16 + l15;
        arb[mf] = abase + r * 128;
        asz[mf] = (r & 7) << 4;
    }
    #pragma unroll
    for (int ng = 0; ng < 4; ++ng) {
        int r = wn * 64 + ng * 16 + l15;
        brb[ng] = bbase + r * 128;
        bsz[ng] = (r & 7) << 4;
    }
    #pragma unroll
    for (int ks = 0; ks < 4; ++ks) {
        uint32_t a[2][4], bq[4][4];
        int cb = ks * 32 + l16;
        #pragma unroll
        for (int mf = 0; mf < 2; ++mf) ldsm4(a[mf], arb[mf] + (cb ^ asz[mf]));
        #pragma unroll
        for (int ng = 0; ng < 4; ++ng) ldsm4(bq[ng], brb[ng] + (cb ^ bsz[ng]));
        #pragma unroll
        for (int mf = 0; mf < 2; ++mf)
            #pragma unroll
            for (int nf = 0; nf < 8; ++nf)
                mma_bf16(acc[mf][nf], a[mf], bq[nf >> 1][nf & 1], bq[nf >> 1][2 + (nf & 1)]);
    }
}

// 3-stage single-sync pipelined mainloop; stage i = [A 16KB][B 16KB] at sb + i*32768.
template <int NCHK, int SPLIT, int AWRAP, int ALD, int BLD>
__device__ __forceinline__ void gemm128(const __nv_bfloat16* __restrict__ Ah,
                                        const __nv_bfloat16* __restrict__ Al,
                                        const __nv_bfloat16* __restrict__ Bsrc,
                                        uint32_t sb, int wm, int wn, int lane,
                                        float (&acc)[2][8][4]) {
    const int tid = threadIdx.x;
    const uint32_t off0 = SWZ((uint32_t)((tid >> 3) * 128 + (tid & 7) * 16));
    const int sA = (tid >> 3) * ALD + (tid & 7) * 8;
    const int sB = (tid >> 3) * BLD + (tid & 7) * 8;

    auto stg = [&](int c, uint32_t base) {
        const __nv_bfloat16* pa =
            ((c < SPLIT) ? Ah + (c % AWRAP) * 64 : Al + ((c - SPLIT) % AWRAP) * 64) + sA;
        const __nv_bfloat16* pb = Bsrc + (size_t)c * 64 + sB;
        #pragma unroll
        for (int i = 0; i < 4; ++i) cpa16(base + off0 + i * 4096, pa + i * 32 * ALD);
        #pragma unroll
        for (int i = 0; i < 4; ++i)
            cpa16(base + 16384 + off0 + i * 4096, pb + i * 32 * BLD);
        cpa_commit();
    };
    auto step = [&](int c, uint32_t cur, uint32_t nxt) {
        cpa_wait<1>();
        __syncthreads();
        if (c + 2 < NCHK) stg(c + 2, nxt);
        compute_chunk(cur, cur + 16384, wm, wn, lane, acc);
    };

    stg(0, sb);
    stg(1, sb + 32768);
    #pragma unroll 1
    for (int c = 0; c < NCHK; c += 3) {
        step(c, sb, sb + 65536);
        step(c + 1, sb + 32768, sb);
        step(c + 2, sb + 65536, sb + 32768);
    }
}

// ---------------- K0: folded B1 (bf16 hi/lo/hi) + bias + zero-scratch ----------
__global__ void k0(const float* __restrict__ Wx, const float* __restrict__ bx,
                   const float* __restrict__ Wfx, const float* __restrict__ bfx,
                   const float* __restrict__ Wsl, const float* __restrict__ bsl,
                   const float* __restrict__ temp) {
    int col = blockIdx.x, d = threadIdx.x;
    {
        int idx = col * 256 + d;
        if (idx < 2 * 8 * 64 * 32) g_num[idx] = 0.f;
        if (idx < 2 * 8 * 64) g_den[idx] = 0.f;
    }
    float v;
    if (col < 512) {
        int h = col >> 6, g = col & 63;
        float s = 0.f;
        #pragma unroll
        for (int c = 0; c < 32; ++c) s += Wx[(h * 32 + c) * 256 + d] * Wsl[g * 32 + c];
        float it = 1.0f / temp[h];
        v = s * it;
        if (d == 0) {
            float sb = bsl[g];
            for (int c = 0; c < 32; ++c) sb += bx[h * 32 + c] * Wsl[g * 32 + c];
            g_bias1[col] = sb * it;
        }
    } else {
        v = Wfx[(col - 512) * 256 + d];
        if (d == 0) g_bias1[col] = bfx[col - 512];
    }
    __nv_bfloat16 h16 = __float2bfloat16(v);
    __nv_bfloat16 l16 = __float2bfloat16(v - __bfloat162float(h16));
    g_B1b[(size_t)col * 768 + d] = h16;
    g_B1b[(size_t)col * 768 + 256 + d] = l16;
    g_B1b[(size_t)col * 768 + 512 + d] = h16;
}

__global__ void kprep(const float* __restrict__ x) {
    size_t base = ((size_t)blockIdx.x * 256 + threadIdx.x) * 8;
    #pragma unroll
    for (int half = 0; half < 2; ++half) {
        size_t i = base + half * 4;
        float4 v = *(const float4*)(x + i);
        __nv_bfloat162 ha, hb, la, lb;
        ha.x = __float2bfloat16(v.x); ha.y = __float2bfloat16(v.y);
        hb.x = __float2bfloat16(v.z); hb.y = __float2bfloat16(v.w);
        la.x = __float2bfloat16(v.x - __bfloat162float(ha.x));
        la.y = __float2bfloat16(v.y - __bfloat162float(ha.y));
        lb.x = __float2bfloat16(v.z - __bfloat162float(hb.x));
        lb.y = __float2bfloat16(v.w - __bfloat162float(hb.y));
        *(uint2*)&g_xh[i] = make_uint2(*(uint32_t*)&ha, *(uint32_t*)&hb);
        *(uint2*)&g_xl[i] = make_uint2(*(uint32_t*)&la, *(uint32_t*)&lb);
    }
}

// ---------------- K1: [128x128] GEMM over K'=768, fused softmax / fx(bf16 hi/lo) -
__global__ __launch_bounds__(256, 2) void k1() {
    extern __shared__ char sm[];
    uint32_t sb = s2u(sm);
    const int tid = threadIdx.x, lane = tid & 31, wid = tid >> 5;
    const int wm = wid & 3, wn = wid >> 2;
    const int y = blockIdx.x;  // 0..5
    const int b = blockIdx.y >> 8, t0 = (blockIdx.y & 255) * 128;
    float* bias = (float*)(sm + 98304);
    if (tid < 128) bias[tid] = g_bias1[y * 128 + tid];

    const __nv_bfloat16* xh = g_xh + (size_t)(b * NN + t0) * 256;
    const __nv_bfloat16* xl = g_xl + (size_t)(b * NN + t0) * 256;
    const __nv_bfloat16* Bsrc = g_B1b + (size_t)(y * 128) * 768;

    float acc[2][8][4];
    #pragma unroll
    for (int i = 0; i < 2; ++i)
        #pragma unroll
        for (int j = 0; j < 8; ++j)
            #pragma unroll
            for (int k = 0; k < 4; ++k) acc[i][j][k] = 0.f;

    gemm128<12, 8, 4, 256, 768>(xh, xl, Bsrc, sb, wm, wn, lane, acc);

    const int q = lane & 3, qr = lane >> 2;
    const int cbl = wn * 64;
    #pragma unroll
    for (int mf = 0; mf < 2; ++mf)
        #pragma unroll
        for (int half = 0; half < 2; ++half) {
            int rl = wm * 32 + mf * 16 + qr + half * 8;
            size_t rb = (size_t)(b * NN + t0 + rl);
            float v[8][2];
            #pragma unroll
            for (int nf = 0; nf < 8; ++nf) {
                v[nf][0] = acc[mf][nf][half * 2 + 0] + bias[cbl + nf * 8 + q * 2 + 0];
                v[nf][1] = acc[mf][nf][half * 2 + 1] + bias[cbl + nf * 8 + q * 2 + 1];
            }
            if (y < 4) {
                float m = v[0][0];
                #pragma unroll
                for (int nf = 0; nf < 8; ++nf) m = fmaxf(m, fmaxf(v[nf][0], v[nf][1]));
                m = fmaxf(m, __shfl_xor_sync(0xffffffffu, m, 1));
                m = fmaxf(m, __shfl_xor_sync(0xffffffffu, m, 2));
                float s = 0.f;
                #pragma unroll
                for (int nf = 0; nf < 8; ++nf) {
                    v[nf][0] = __expf(v[nf][0] - m);
                    v[nf][1] = __expf(v[nf][1] - m);
                    s += v[nf][0] + v[nf][1];
                }
                s += __shfl_xor_sync(0xffffffffu, s, 1);
                s += __shfl_xor_sync(0xffffffffu, s, 2);
                float inv = 1.0f / s;
                size_t base = rb * 512 + y * 128 + cbl;
                #pragma unroll
                for (int nf = 0; nf < 8; ++nf) {
                    float a = v[nf][0] * inv, bq2 = v[nf][1] * inv;
                    __nv_bfloat162 hp, lp;
                    hp.x = __float2bfloat16(a); hp.y = __float2bfloat16(bq2);
                    lp.x = __float2bfloat16(a - __bfloat162float(hp.x));
                    lp.y = __float2bfloat16(bq2 - __bfloat162float(hp.y));
                    *(uint32_t*)&g_swh[base + nf * 8 + q * 2] = *(uint32_t*)&hp;
                    *(uint32_t*)&g_swl[base + nf * 8 + q * 2] = *(uint32_t*)&lp;
                }
            } else {
                size_t base = rb * 256 + (y - 4) * 128 + cbl;
                #pragma unroll
                for (int nf = 0; nf < 8; ++nf) {
                    __nv_bfloat162 hp, lp;
                    hp.x = __float2bfloat16(v[nf][0]);
                    hp.y = __float2bfloat16(v[nf][1]);
                    lp.x = __float2bfloat16(v[nf][0] - __bfloat162float(hp.x));
                    lp.y = __float2bfloat16(v[nf][1] - __bfloat162float(hp.y));
                    *(uint32_t*)&g_fxh[base + nf * 8 + q * 2] = *(uint32_t*)&hp;
                    *(uint32_t*)&g_fxl[base + nf * 8 + q * 2] = *(uint32_t*)&lp;
                }
            }
        }
}

// ---------------- K2: num = sw^T @ fx via tensor cores; 128 K-slices ------------
__global__ __launch_bounds__(256) void k2() {
    extern __shared__ char sm[];
    const uint32_t sb = s2u(sm);
    const int bh = blockIdx.y, b = bh >> 3, h = bh & 7;
    const int n0 = blockIdx.x * 256;
    const int tid = threadIdx.x, lane = tid & 31, wid = tid >> 5;
    const int mt = wid & 3, np = wid >> 2;

    const int rr = tid >> 3, p8 = tid & 7;
    const int fr = (tid & 127) >> 2, fp = tid & 3;
    const int fsel = tid >> 7;
    const uint32_t d_swh = sb + rr * 144 + p8 * 16;
    const uint32_t d_swl = d_swh + 4608;
    const uint32_t d_fx = sb + 9216 + fsel * 2560 + fr * 80 + fp * 16;
    const __nv_bfloat16* s_swh = &g_swh[((size_t)(b * NN + n0 + rr)) * 512 + h * 64 + p8 * 8];
    const __nv_bfloat16* s_swl = &g_swl[((size_t)(b * NN + n0 + rr)) * 512 + h * 64 + p8 * 8];
    const __nv_bfloat16* s_fx =
        (fsel ? g_fxl : g_fxh) + ((size_t)(b * NN + n0 + fr)) * 256 + h * 32 + fp * 8;

    auto stg = [&](int s) {
        uint32_t so = (s & 3) * 14336;
        cpa16(d_swh + so, s_swh + (size_t)s * 32 * 512);
        cpa16(d_swl + so, s_swl + (size_t)s * 32 * 512);
        cpa16(d_fx + so, s_fx + (size_t)s * 32 * 256);
        cpa_commit();
    };

    const uint32_t a_off = (uint32_t)(((lane & 7) + ((lane >> 4) & 1) * 8) * 144 +
                                      (mt * 16 + ((lane >> 3) & 1) * 8) * 2);
    const uint32_t b_off = (uint32_t)(9216 + ((lane & 7) + ((lane >> 4) & 1) * 8) * 80 +
                                      (np * 16 + ((lane >> 3) & 1) * 8) * 2);
    const int dg = mt * 16 + (lane & 15);
    const int dr0 = (lane >> 4) * 16;

    float acc[2][4] = {{0.f, 0.f, 0.f, 0.f}, {0.f, 0.f, 0.f, 0.f}};
    float dden = 0.f;

    stg(0); stg(1); stg(2);
    #pragma unroll 1
    for (int c = 0; c < 8; ++c) {
        cpa_wait<2>();
        __syncthreads();
        if (c + 3 < 8) stg(c + 3); else cpa_commit();
        const uint32_t st = sb + (c & 3) * 14336;
        #pragma unroll
        for (int s16 = 0; s16 < 2; ++s16) {
            uint32_t ah[4], al[4], bhf[4], blf[4];
            ldsm4t(ah, st + a_off + s16 * 2304);
            ldsm4t(al, st + a_off + 4608 + s16 * 2304);
            ldsm4t(bhf, st + b_off + s16 * 1280);
            ldsm4t(blf, st + b_off + 2560 + s16 * 1280);
            #pragma unroll
            for (int nt = 0; nt < 2; ++nt) {
                mma_bf16(acc[nt], ah, bhf[nt], bhf[2 + nt]);
                mma_bf16(acc[nt], ah, blf[nt], blf[2 + nt]);
                mma_bf16(acc[nt], al, bhf[nt], bhf[2 + nt]);
            }
        }
        if (np == 0) {
            const char* sp = sm + (c & 3) * 14336;
            float ds = 0.f;
            #pragma unroll
            for (int r = 0; r < 16; ++r) {
                int row = dr0 + r;
                ds += __bfloat162float(*(const __nv_bfloat16*)(sp + row * 144 + dg * 2));
                ds += __bfloat162float(*(const __nv_bfloat16*)(sp + 4608 + row * 144 + dg * 2));
            }
            dden += ds;
        }
    }
    dden += __shfl_xor_sync(0xffffffffu, dden, 16);
    if (np == 0 && lane < 16) atomicAdd(&g_den[bh * 64 + dg], dden);
    #pragma unroll
    for (int nt = 0; nt < 2; ++nt)
        #pragma unroll
        for (int j = 0; j < 4; ++j) {
            int g = mt * 16 + (lane >> 2) + (j >> 1) * 8;
            int cc = np * 16 + nt * 8 + (lane & 3) * 2 + (j & 1);
            atomicAdd(&g_num[(bh * 64 + g) * 32 + cc], acc[nt][j]);
        }
}

// ---------------- K3: slice_att -> qkv -> SDPA -> fold Wout -> g_Mb -------------
__global__ __launch_bounds__(256) void k3(const float* __restrict__ Wqkv,
                                          const float* __restrict__ Wout) {
    __shared__ float S[11264];
    float* sa = S;
    float* wq = S + 2048;
    float* qs = S + 5120;
    float* ks2 = S + 7168;
    float* vs = S + 9216;
    float* sc = S;
    float* att = S + 5120;
    const int bh = blockIdx.x, b = bh >> 3, h = bh & 7;
    const int tid = threadIdx.x;
    for (int i = tid; i < 3072; i += 256) wq[i] = Wqkv[i];
    #pragma unroll
    for (int c = 0; c < 8; ++c) {
        int idx = tid * 8 + c;
        sa[idx] = g_num[bh * 2048 + idx] / (g_den[bh * 64 + (idx >> 5)] + 1e-5f);
    }
    __syncthreads();
    for (int t = tid; t < 6144; t += 256) {
        int g = t & 63, j = t >> 6;
        float s2 = 0.f;
        #pragma unroll
        for (int c = 0; c < 32; ++c) s2 += sa[g * 32 + c] * wq[j * 32 + c];
        if (j < 32) qs[g * 32 + j] = s2;
        else if (j < 64) ks2[g * 32 + (j - 32)] = s2;
        else vs[g * 32 + (j - 64)] = s2;
    }
    __syncthreads();
    for (int t = tid; t < 4096; t += 256) {
        int g = t >> 6, kk = t & 63;
        float s2 = 0.f;
        #pragma unroll
        for (int c = 0; c < 32; ++c) s2 += qs[g * 32 + c] * ks2[kk * 32 + c];
        sc[g * 65 + kk] = s2 * 0.17677669529663687f;
    }
    __syncthreads();
    if (tid < 64) {
        int g = tid;
        float m = -1e30f;
        #pragma unroll 8
        for (int kk = 0; kk < 64; ++kk) m = fmaxf(m, sc[g * 65 + kk]);
        float ssum = 0.f;
        #pragma unroll 8
        for (int kk = 0; kk < 64; ++kk) {
            float e = __expf(sc[g * 65 + kk] - m);
            sc[g * 65 + kk] = e;
            ssum += e;
        }
        float inv = 1.0f / ssum;
        #pragma unroll 8
        for (int kk = 0; kk < 64; ++kk) sc[g * 65 + kk] *= inv;
    }
    __syncthreads();
    for (int t = tid; t < 2048; t += 256) {
        int g = t >> 5, c = t & 31;
        float a = 0.f;
        #pragma unroll 8
        for (int kk = 0; kk < 64; ++kk) a += sc[g * 65 + kk] * vs[kk * 32 + c];
        att[g * 32 + c] = a;
    }
    __syncthreads();
    int d2 = tid;
    float wl[32];
    #pragma unroll
    for (int c = 0; c < 32; ++c) wl[c] = Wout[d2 * 256 + h * 32 + c];
    for (int g = 0; g < 64; ++g) {
        float s2 = 0.f;
        #pragma unroll
        for (int c = 0; c < 32; ++c) s2 += att[g * 32 + c] * wl[c];
        __nv_bfloat16 h16 = __float2bfloat16(s2);
        __nv_bfloat16 l16 = __float2bfloat16(s2 - __bfloat162float(h16));
        size_t o0 = (size_t)b * 256 * 1536 + (size_t)d2 * 1536 + h * 64 + g;
        g_Mb[o0] = h16;
        g_Mb[o0 + 512] = l16;
        g_Mb[o0 + 1024] = h16;
    }
}

// ---------------- K4: out = sw @ M + bout ([128x128] tile, K'=1536) --------------
__global__ __launch_bounds__(256, 2) void k4(float* __restrict__ out,
                                             const float* __restrict__ bout) {
    extern __shared__ char sm[];
    uint32_t sb = s2u(sm);
    const int tid = threadIdx.x, lane = tid & 31, wid = tid >> 5;
    const int wm = wid & 3, wn = wid >> 2;
    const int y = blockIdx.x;  // 0..1
    const int b = blockIdx.y >> 8, t0 = (blockIdx.y & 255) * 128;
    float* bias = (float*)(sm + 98304);
    if (tid < 128) bias[tid] = bout[y * 128 + tid];

    const __nv_bfloat16* swh = g_swh + (size_t)(b * NN + t0) * 512;
    const __nv_bfloat16* swl = g_swl + (size_t)(b * NN + t0) * 512;
    const __nv_bfloat16* Bsrc = g_Mb + (size_t)b * 256 * 1536 + (size_t)(y * 128) * 1536;

    float acc[2][8][4];
    #pragma unroll
    for (int i = 0; i < 2; ++i)
        #pragma unroll
        for (int j = 0; j < 8; ++j)
            #pragma unroll
            for (int k = 0; k < 4; ++k) acc[i][j][k] = 0.f;

    gemm128<24, 16, 8, 512, 1536>(swh, swl, Bsrc, sb, wm, wn, lane, acc);

    const int q = lane & 3, qr = lane >> 2;
    const int cbl = wn * 64;
    #pragma unroll
    for (int mf = 0; mf < 2; ++mf)
        #pragma unroll
        for (int half = 0; half < 2; ++half) {
            int rl = wm * 32 + mf * 16 + qr + half * 8;
            float* op = out + (size_t)(b * NN + t0 + rl) * 256 + y * 128 + cbl;
            #pragma unroll
            for (int nf = 0; nf < 8; ++nf) {
                float v0 = acc[mf][nf][half * 2 + 0] + bias[cbl + nf * 8 + q * 2 + 0];
                float v1 = acc[mf][nf][half * 2 + 1] + bias[cbl + nf * 8 + q * 2 + 1];
                *(float2*)(op + nf * 8 + q * 2) = make_float2(v0, v1);
            }
        }
}

extern "C" void kernel_launch(void* const* d_in, const int* in_sizes, int n_in,
                              void* d_out, int out_size) {
    const float* x = (const float*)d_in[0];
    const float* Wx = (const float*)d_in[1];
    const float* bx = (const float*)d_in[2];
    const float* Wfx = (const float*)d_in[3];
    const float* bfx = (const float*)d_in[4];
    const float* Wsl = (const float*)d_in[5];
    const float* bsl = (const float*)d_in[6];
    const float* temp = (const float*)d_in[7];
    const float* Wqkv = (const float*)d_in[8];
    const float* Wout = (const float*)d_in[9];
    const float* bout = (const float*)d_in[10];
    float* out = (float*)d_out;

    const int SMEM = 98304 + 512;  // 3 stages x 32KB + bias
    cudaFuncSetAttribute(k1, cudaFuncAttributeMaxDynamicSharedMemorySize, SMEM);
    cudaFuncSetAttribute(k4, cudaFuncAttributeMaxDynamicSharedMemorySize, SMEM);
    const int SMEM2 = 4 * 14336;  // 57344
    cudaFuncSetAttribute(k2, cudaFuncAttributeMaxDynamicSharedMemorySize, SMEM2);

    k0<<<768, 256>>>(Wx, bx, Wfx, bfx, Wsl, bsl, temp);
    kprep<<<8192, 256>>>(x);
    k1<<<dim3(6, 512), 256, SMEM>>>();
    k2<<<dim3(128, 16), 256, SMEM2>>>();
    k3<<<16, 256>>>(Wqkv, Wout);
    k4<<<dim3(2, 512), 256, SMEM>>>(out, bout);
}

// round 17
// speedup vs baseline: 1.0006x; 1.0006x over previous
#include <cuda_runtime.h>
#include <cuda_bf16.h>
#include <cstdint>

#define NN 32768
#define SWZ(o) ((o) ^ (((o) >> 3) & 0x70))

__device__ __align__(128) __nv_bfloat16 g_xh[(size_t)2 * NN * 256];
__device__ __align__(128) __nv_bfloat16 g_xl[(size_t)2 * NN * 256];
__device__ __align__(128) __nv_bfloat16 g_B1b[768u * 768];
__device__ __align__(128) float g_bias1[768];
__device__ __align__(128) __nv_bfloat16 g_swh[(size_t)2 * NN * 512];
__device__ __align__(128) __nv_bfloat16 g_swl[(size_t)2 * NN * 512];
__device__ __align__(128) __nv_bfloat16 g_fxh[(size_t)2 * NN * 256];
__device__ __align__(128) __nv_bfloat16 g_fxl[(size_t)2 * NN * 256];
__device__ __align__(128) float g_num[2 * 8 * 64 * 32];
__device__ __align__(128) float g_den[2 * 8 * 64];
__device__ __align__(128) __nv_bfloat16 g_Mb[(size_t)2 * 256 * 1536];

__device__ __forceinline__ uint32_t s2u(const void* p) {
    uint32_t a;
    asm("{ .reg .u64 t; cvta.to.shared.u64 t, %1; cvt.u32.u64 %0, t; }" : "=r"(a) : "l"(p));
    return a;
}
__device__ __forceinline__ void cpa16(uint32_t dst, const void* src) {
    asm volatile("cp.async.cg.shared.global [%0], [%1], 16;" :: "r"(dst), "l"(src));
}
__device__ __forceinline__ void cpa_commit() { asm volatile("cp.async.commit_group;" ::: "memory"); }
template <int N>
__device__ __forceinline__ void cpa_wait() { asm volatile("cp.async.wait_group %0;" :: "n"(N) : "memory"); }

__device__ __forceinline__ void ldsm4(uint32_t* r, uint32_t addr) {
    asm volatile("ldmatrix.sync.aligned.m8n8.x4.shared.b16 {%0,%1,%2,%3}, [%4];"
                 : "=r"(r[0]), "=r"(r[1]), "=r"(r[2]), "=r"(r[3]) : "r"(addr));
}
__device__ __forceinline__ void ldsm4t(uint32_t* r, uint32_t addr) {
    asm volatile("ldmatrix.sync.aligned.m8n8.x4.trans.shared.b16 {%0,%1,%2,%3}, [%4];"
                 : "=r"(r[0]), "=r"(r[1]), "=r"(r[2]), "=r"(r[3]) : "r"(addr));
}
__device__ __forceinline__ void mma_bf16(float* c, const uint32_t* a, uint32_t b0, uint32_t b1) {
    asm volatile("mma.sync.aligned.m16n8k16.row.col.f32.bf16.bf16.f32 "
                 "{%0,%1,%2,%3},{%4,%5,%6,%7},{%8,%9},{%0,%1,%2,%3};"
                 : "+f"(c[0]), "+f"(c[1]), "+f"(c[2]), "+f"(c[3])
                 : "r"(a[0]), "r"(a[1]), "r"(a[2]), "r"(a[3]), "r"(b0), "r"(b1));
}

// one 64-k chunk: warp (wm 0..3, wn 0..1) computes 32x64 of the 128x128 tile
__device__ __forceinline__ void compute_chunk(uint32_t abase, uint32_t bbase, int wm, int wn,
                                              int lane, float (&acc)[2][8][4]) {
    const int l15 = lane & 15, l16 = (lane >> 4) << 4;
    uint32_t arb[2], brb[4];
    int asz[2], bsz[4];
    #pragma unroll
    for (int mf = 0; mf < 2; ++mf) {
        int r = wm * 32 + mf * 16 + l15;
        arb[mf] = abase + r * 128;
        asz[mf] = (r & 7) << 4;
    }
    #pragma unroll
    for (int ng = 0; ng < 4; ++ng) {
        int r = wn * 64 + ng * 16 + l15;
        brb[ng] = bbase + r * 128;
        bsz[ng] = (r & 7) << 4;
    }
    #pragma unroll
    for (int ks = 0; ks < 4; ++ks) {
        uint32_t a[2][4], bq[4][4];
        int cb = ks * 32 + l16;
        #pragma unroll
        for (int mf = 0; mf < 2; ++mf) ldsm4(a[mf], arb[mf] + (cb ^ asz[mf]));
        #pragma unroll
        for (int ng = 0; ng < 4; ++ng) ldsm4(bq[ng], brb[ng] + (cb ^ bsz[ng]));
        #pragma unroll
        for (int mf = 0; mf < 2; ++mf)
            #pragma unroll
            for (int nf = 0; nf < 8; ++nf)
                mma_bf16(acc[mf][nf], a[mf], bq[nf >> 1][nf & 1], bq[nf >> 1][2 + (nf & 1)]);
    }
}

// 3-stage single-sync pipelined mainloop; stage i = [A 16KB][B 16KB] at sb + i*32768.
template <int NCHK, int SPLIT, int AWRAP, int ALD, int BLD>
__device__ __forceinline__ void gemm128(const __nv_bfloat16* __restrict__ Ah,
                                        const __nv_bfloat16* __restrict__ Al,
                                        const __nv_bfloat16* __restrict__ Bsrc,
                                        uint32_t sb, int wm, int wn, int lane,
                                        float (&acc)[2][8][4]) {
    const int tid = threadIdx.x;
    const uint32_t off0 = SWZ((uint32_t)((tid >> 3) * 128 + (tid & 7) * 16));
    const int sA = (tid >> 3) * ALD + (tid & 7) * 8;
    const int sB = (tid >> 3) * BLD + (tid & 7) * 8;

    auto stg = [&](int c, uint32_t base) {
        const __nv_bfloat16* pa =
            ((c < SPLIT) ? Ah + (c % AWRAP) * 64 : Al + ((c - SPLIT) % AWRAP) * 64) + sA;
        const __nv_bfloat16* pb = Bsrc + (size_t)c * 64 + sB;
        #pragma unroll
        for (int i = 0; i < 4; ++i) cpa16(base + off0 + i * 4096, pa + i * 32 * ALD);
        #pragma unroll
        for (int i = 0; i < 4; ++i)
            cpa16(base + 16384 + off0 + i * 4096, pb + i * 32 * BLD);
        cpa_commit();
    };
    auto step = [&](int c, uint32_t cur, uint32_t nxt) {
        cpa_wait<1>();
        __syncthreads();
        if (c + 2 < NCHK) stg(c + 2, nxt);
        compute_chunk(cur, cur + 16384, wm, wn, lane, acc);
    };

    stg(0, sb);
    stg(1, sb + 32768);
    #pragma unroll 1
    for (int c = 0; c < NCHK; c += 3) {
        step(c, sb, sb + 65536);
        step(c + 1, sb + 32768, sb);
        step(c + 2, sb + 65536, sb + 32768);
    }
}

// ---------------- K0: folded B1 (bf16 hi/lo/hi) + bias + zero-scratch ----------
__global__ void k0(const float* __restrict__ Wx, const float* __restrict__ bx,
                   const float* __restrict__ Wfx, const float* __restrict__ bfx,
                   const float* __restrict__ Wsl, const float* __restrict__ bsl,
                   const float* __restrict__ temp) {
    int col = blockIdx.x, d = threadIdx.x;
    {
        int idx = col * 256 + d;
        if (idx < 2 * 8 * 64 * 32) g_num[idx] = 0.f;
        if (idx < 2 * 8 * 64) g_den[idx] = 0.f;
    }
    float v;
    if (col < 512) {
        int h = col >> 6, g = col & 63;
        float s = 0.f;
        #pragma unroll
        for (int c = 0; c < 32; ++c) s += Wx[(h * 32 + c) * 256 + d] * Wsl[g * 32 + c];
        float it = 1.0f / temp[h];
        v = s * it;
        if (d == 0) {
            float sb = bsl[g];
            for (int c = 0; c < 32; ++c) sb += bx[h * 32 + c] * Wsl[g * 32 + c];
            g_bias1[col] = sb * it;
        }
    } else {
        v = Wfx[(col - 512) * 256 + d];
        if (d == 0) g_bias1[col] = bfx[col - 512];
    }
    __nv_bfloat16 h16 = __float2bfloat16(v);
    __nv_bfloat16 l16 = __float2bfloat16(v - __bfloat162float(h16));
    g_B1b[(size_t)col * 768 + d] = h16;
    g_B1b[(size_t)col * 768 + 256 + d] = l16;
    g_B1b[(size_t)col * 768 + 512 + d] = h16;
}

__global__ void kprep(const float* __restrict__ x) {
    size_t base = ((size_t)blockIdx.x * 256 + threadIdx.x) * 8;
    #pragma unroll
    for (int half = 0; half < 2; ++half) {
        size_t i = base + half * 4;
        float4 v = *(const float4*)(x + i);
        __nv_bfloat162 ha, hb, la, lb;
        ha.x = __float2bfloat16(v.x); ha.y = __float2bfloat16(v.y);
        hb.x = __float2bfloat16(v.z); hb.y = __float2bfloat16(v.w);
        la.x = __float2bfloat16(v.x - __bfloat162float(ha.x));
        la.y = __float2bfloat16(v.y - __bfloat162float(ha.y));
        lb.x = __float2bfloat16(v.z - __bfloat162float(hb.x));
        lb.y = __float2bfloat16(v.w - __bfloat162float(hb.y));
        *(uint2*)&g_xh[i] = make_uint2(*(uint32_t*)&ha, *(uint32_t*)&hb);
        *(uint2*)&g_xl[i] = make_uint2(*(uint32_t*)&la, *(uint32_t*)&lb);
    }
}

// ---------------- K1: [128x128] GEMM over K'=768, fused softmax / fx(bf16 hi/lo) -
__global__ __launch_bounds__(256, 2) void k1() {
    extern __shared__ char sm[];
    uint32_t sb = s2u(sm);
    const int tid = threadIdx.x, lane = tid & 31, wid = tid >> 5;
    const int wm = wid & 3, wn = wid >> 2;
    const int y = blockIdx.x;  // 0..5
    const int b = blockIdx.y >> 8, t0 = (blockIdx.y & 255) * 128;
    float* bias = (float*)(sm + 98304);
    if (tid < 128) bias[tid] = g_bias1[y * 128 + tid];

    const __nv_bfloat16* xh = g_xh + (size_t)(b * NN + t0) * 256;
    const __nv_bfloat16* xl = g_xl + (size_t)(b * NN + t0) * 256;
    const __nv_bfloat16* Bsrc = g_B1b + (size_t)(y * 128) * 768;

    float acc[2][8][4];
    #pragma unroll
    for (int i = 0; i < 2; ++i)
        #pragma unroll
        for (int j = 0; j < 8; ++j)
            #pragma unroll
            for (int k = 0; k < 4; ++k) acc[i][j][k] = 0.f;

    gemm128<12, 8, 4, 256, 768>(xh, xl, Bsrc, sb, wm, wn, lane, acc);

    const int q = lane & 3, qr = lane >> 2;
    const int cbl = wn * 64;
    #pragma unroll
    for (int mf = 0; mf < 2; ++mf)
        #pragma unroll
        for (int half = 0; half < 2; ++half) {
            int rl = wm * 32 + mf * 16 + qr + half * 8;
            size_t rb = (size_t)(b * NN + t0 + rl);
            float v[8][2];
            #pragma unroll
            for (int nf = 0; nf < 8; ++nf) {
                v[nf][0] = acc[mf][nf][half * 2 + 0] + bias[cbl + nf * 8 + q * 2 + 0];
                v[nf][1] = acc[mf][nf][half * 2 + 1] + bias[cbl + nf * 8 + q * 2 + 1];
            }
            if (y < 4) {
                float m = v[0][0];
                #pragma unroll
                for (int nf = 0; nf < 8; ++nf) m = fmaxf(m, fmaxf(v[nf][0], v[nf][1]));
                m = fmaxf(m, __shfl_xor_sync(0xffffffffu, m, 1));
                m = fmaxf(m, __shfl_xor_sync(0xffffffffu, m, 2));
                float s = 0.f;
                #pragma unroll
                for (int nf = 0; nf < 8; ++nf) {
                    v[nf][0] = __expf(v[nf][0] - m);
                    v[nf][1] = __expf(v[nf][1] - m);
                    s += v[nf][0] + v[nf][1];
                }
                s += __shfl_xor_sync(0xffffffffu, s, 1);
                s += __shfl_xor_sync(0xffffffffu, s, 2);
                float inv = 1.0f / s;
                size_t base = rb * 512 + y * 128 + cbl;
                #pragma unroll
                for (int nf = 0; nf < 8; ++nf) {
                    float a = v[nf][0] * inv, bq2 = v[nf][1] * inv;
                    __nv_bfloat162 hp, lp;
                    hp.x = __float2bfloat16(a); hp.y = __float2bfloat16(bq2);
                    lp.x = __float2bfloat16(a - __bfloat162float(hp.x));
                    lp.y = __float2bfloat16(bq2 - __bfloat162float(hp.y));
                    *(uint32_t*)&g_swh[base + nf * 8 + q * 2] = *(uint32_t*)&hp;
                    *(uint32_t*)&g_swl[base + nf * 8 + q * 2] = *(uint32_t*)&lp;
                }
            } else {
                size_t base = rb * 256 + (y - 4) * 128 + cbl;
                #pragma unroll
                for (int nf = 0; nf < 8; ++nf) {
                    __nv_bfloat162 hp, lp;
                    hp.x = __float2bfloat16(v[nf][0]);
                    hp.y = __float2bfloat16(v[nf][1]);
                    lp.x = __float2bfloat16(v[nf][0] - __bfloat162float(hp.x));
                    lp.y = __float2bfloat16(v[nf][1] - __bfloat162float(hp.y));
                    *(uint32_t*)&g_fxh[base + nf * 8 + q * 2] = *(uint32_t*)&hp;
                    *(uint32_t*)&g_fxl[base + nf * 8 + q * 2] = *(uint32_t*)&lp;
                }
            }
        }
}

// ---------------- K2: num = sw^T @ fx via tensor cores; 64 K-slices, 5-buf ring --
__global__ __launch_bounds__(256) void k2() {
    extern __shared__ char sm[];
    const uint32_t sb = s2u(sm);
    const int bh = blockIdx.y, b = bh >> 3, h = bh & 7;
    const int n0 = blockIdx.x * 512;
    const int tid = threadIdx.x, lane = tid & 31, wid = tid >> 5;
    const int mt = wid & 3, np = wid >> 2;

    const int rr = tid >> 3, p8 = tid & 7;
    const int fr = (tid & 127) >> 2, fp = tid & 3;
    const int fsel = tid >> 7;
    const uint32_t d_swh = sb + rr * 144 + p8 * 16;
    const uint32_t d_swl = d_swh + 4608;
    const uint32_t d_fx = sb + 9216 + fsel * 2560 + fr * 80 + fp * 16;
    const __nv_bfloat16* s_swh = &g_swh[((size_t)(b * NN + n0 + rr)) * 512 + h * 64 + p8 * 8];
    const __nv_bfloat16* s_swl = &g_swl[((size_t)(b * NN + n0 + rr)) * 512 + h * 64 + p8 * 8];
    const __nv_bfloat16* s_fx =
        (fsel ? g_fxl : g_fxh) + ((size_t)(b * NN + n0 + fr)) * 256 + h * 32 + fp * 8;

    auto stg = [&](int s) {
        uint32_t so = (uint32_t)(s % 5) * 14336;
        cpa16(d_swh + so, s_swh + (size_t)s * 32 * 512);
        cpa16(d_swl + so, s_swl + (size_t)s * 32 * 512);
        cpa16(d_fx + so, s_fx + (size_t)s * 32 * 256);
        cpa_commit();
    };

    const uint32_t a_off = (uint32_t)(((lane & 7) + ((lane >> 4) & 1) * 8) * 144 +
                                      (mt * 16 + ((lane >> 3) & 1) * 8) * 2);
    const uint32_t b_off = (uint32_t)(9216 + ((lane & 7) + ((lane >> 4) & 1) * 8) * 80 +
                                      (np * 16 + ((lane >> 3) & 1) * 8) * 2);
    const int dg = mt * 16 + (lane & 15);
    const int dr0 = (lane >> 4) * 16;

    float acc[2][4] = {{0.f, 0.f, 0.f, 0.f}, {0.f, 0.f, 0.f, 0.f}};
    float dden = 0.f;

    stg(0); stg(1); stg(2); stg(3);
    #pragma unroll 1
    for (int c = 0; c < 16; ++c) {
        cpa_wait<3>();
        __syncthreads();
        if (c + 4 < 16) stg(c + 4); else cpa_commit();
        const uint32_t st = sb + (uint32_t)(c % 5) * 14336;
        #pragma unroll
        for (int s16 = 0; s16 < 2; ++s16) {
            uint32_t ah[4], al[4], bhf[4], blf[4];
            ldsm4t(ah, st + a_off + s16 * 2304);
            ldsm4t(al, st + a_off + 4608 + s16 * 2304);
            ldsm4t(bhf, st + b_off + s16 * 1280);
            ldsm4t(blf, st + b_off + 2560 + s16 * 1280);
            #pragma unroll
            for (int nt = 0; nt < 2; ++nt) {
                mma_bf16(acc[nt], ah, bhf[nt], bhf[2 + nt]);
                mma_bf16(acc[nt], ah, blf[nt], blf[2 + nt]);
                mma_bf16(acc[nt], al, bhf[nt], bhf[2 + nt]);
            }
        }
        if (np == 0) {
            const char* sp = sm + (size_t)(c % 5) * 14336;
            float ds = 0.f;
            #pragma unroll
            for (int r = 0; r < 16; ++r) {
                int row = dr0 + r;
                ds += __bfloat162float(*(const __nv_bfloat16*)(sp + row * 144 + dg * 2));
                ds += __bfloat162float(*(const __nv_bfloat16*)(sp + 4608 + row * 144 + dg * 2));
            }
            dden += ds;
        }
    }
    dden += __shfl_xor_sync(0xffffffffu, dden, 16);
    if (np == 0 && lane < 16) atomicAdd(&g_den[bh * 64 + dg], dden);
    #pragma unroll
    for (int nt = 0; nt < 2; ++nt)
        #pragma unroll
        for (int j = 0; j < 4; ++j) {
            int g = mt * 16 + (lane >> 2) + (j >> 1) * 8;
            int cc = np * 16 + nt * 8 + (lane & 3) * 2 + (j & 1);
            atomicAdd(&g_num[(bh * 64 + g) * 32 + cc], acc[nt][j]);
        }
}

// ---------------- K3: slice_att -> qkv -> SDPA -> fold Wout -> g_Mb -------------
__global__ __launch_bounds__(256) void k3(const float* __restrict__ Wqkv,
                                          const float* __restrict__ Wout) {
    __shared__ float S[11264];
    float* sa = S;
    float* wq = S + 2048;
    float* qs = S + 5120;
    float* ks2 = S + 7168;
    float* vs = S + 9216;
    float* sc = S;
    float* att = S + 5120;
    const int bh = blockIdx.x, b = bh >> 3, h = bh & 7;
    const int tid = threadIdx.x;
    for (int i = tid; i < 3072; i += 256) wq[i] = Wqkv[i];
    #pragma unroll
    for (int c = 0; c < 8; ++c) {
        int idx = tid * 8 + c;
        sa[idx] = g_num[bh * 2048 + idx] / (g_den[bh * 64 + (idx >> 5)] + 1e-5f);
    }
    __syncthreads();
    for (int t = tid; t < 6144; t += 256) {
        int g = t & 63, j = t >> 6;
        float s2 = 0.f;
        #pragma unroll
        for (int c = 0; c < 32; ++c) s2 += sa[g * 32 + c] * wq[j * 32 + c];
        if (j < 32) qs[g * 32 + j] = s2;
        else if (j < 64) ks2[g * 32 + (j - 32)] = s2;
        else vs[g * 32 + (j - 64)] = s2;
    }
    __syncthreads();
    for (int t = tid; t < 4096; t += 256) {
        int g = t >> 6, kk = t & 63;
        float s2 = 0.f;
        #pragma unroll
        for (int c = 0; c < 32; ++c) s2 += qs[g * 32 + c] * ks2[kk * 32 + c];
        sc[g * 65 + kk] = s2 * 0.17677669529663687f;
    }
    __syncthreads();
    if (tid < 64) {
        int g = tid;
        float m = -1e30f;
        #pragma unroll 8
        for (int kk = 0; kk < 64; ++kk) m = fmaxf(m, sc[g * 65 + kk]);
        float ssum = 0.f;
        #pragma unroll 8
        for (int kk = 0; kk < 64; ++kk) {
            float e = __expf(sc[g * 65 + kk] - m);
            sc[g * 65 + kk] = e;
            ssum += e;
        }
        float inv = 1.0f / ssum;
        #pragma unroll 8
        for (int kk = 0; kk < 64; ++kk) sc[g * 65 + kk] *= inv;
    }
    __syncthreads();
    for (int t = tid; t < 2048; t += 256) {
        int g = t >> 5, c = t & 31;
        float a = 0.f;
        #pragma unroll 8
        for (int kk = 0; kk < 64; ++kk) a += sc[g * 65 + kk] * vs[kk * 32 + c];
        att[g * 32 + c] = a;
    }
    __syncthreads();
    int d2 = tid;
    float wl[32];
    #pragma unroll
    for (int c = 0; c < 32; ++c) wl[c] = Wout[d2 * 256 + h * 32 + c];
    for (int g = 0; g < 64; ++g) {
        float s2 = 0.f;
        #pragma unroll
        for (int c = 0; c < 32; ++c) s2 += att[g * 32 + c] * wl[c];
        __nv_bfloat16 h16 = __float2bfloat16(s2);
        __nv_bfloat16 l16 = __float2bfloat16(s2 - __bfloat162float(h16));
        size_t o0 = (size_t)b * 256 * 1536 + (size_t)d2 * 1536 + h * 64 + g;
        g_Mb[o0] = h16;
        g_Mb[o0 + 512] = l16;
        g_Mb[o0 + 1024] = h16;
    }
}

// ---------------- K4: out = sw @ M + bout ([128x128] tile, K'=1536) --------------
__global__ __launch_bounds__(256, 2) void k4(float* __restrict__ out,
                                             const float* __restrict__ bout) {
    extern __shared__ char sm[];
    uint32_t sb = s2u(sm);
    const int tid = threadIdx.x, lane = tid & 31, wid = tid >> 5;
    const int wm = wid & 3, wn = wid >> 2;
    const int y = blockIdx.x;  // 0..1
    const int b = blockIdx.y >> 8, t0 = (blockIdx.y & 255) * 128;
    float* bias = (float*)(sm + 98304);
    if (tid < 128) bias[tid] = bout[y * 128 + tid];

    const __nv_bfloat16* swh = g_swh + (size_t)(b * NN + t0) * 512;
    const __nv_bfloat16* swl = g_swl + (size_t)(b * NN + t0) * 512;
    const __nv_bfloat16* Bsrc = g_Mb + (size_t)b * 256 * 1536 + (size_t)(y * 128) * 1536;

    float acc[2][8][4];
    #pragma unroll
    for (int i = 0; i < 2; ++i)
        #pragma unroll
        for (int j = 0; j < 8; ++j)
            #pragma unroll
            for (int k = 0; k < 4; ++k) acc[i][j][k] = 0.f;

    gemm128<24, 16, 8, 512, 1536>(swh, swl, Bsrc, sb, wm, wn, lane, acc);

    const int q = lane & 3, qr = lane >> 2;
    const int cbl = wn * 64;
    #pragma unroll
    for (int mf = 0; mf < 2; ++mf)
        #pragma unroll
        for (int half = 0; half < 2; ++half) {
            int rl = wm * 32 + mf * 16 + qr + half * 8;
            float* op = out + (size_t)(b * NN + t0 + rl) * 256 + y * 128 + cbl;
            #pragma unroll
            for (int nf = 0; nf < 8; ++nf) {
                float v0 = acc[mf][nf][half * 2 + 0] + bias[cbl + nf * 8 + q * 2 + 0];
                float v1 = acc[mf][nf][half * 2 + 1] + bias[cbl + nf * 8 + q * 2 + 1];
                *(float2*)(op + nf * 8 + q * 2) = make_float2(v0, v1);
            }
        }
}

extern "C" void kernel_launch(void* const* d_in, const int* in_sizes, int n_in,
                              void* d_out, int out_size) {
    const float* x = (const float*)d_in[0];
    const float* Wx = (const float*)d_in[1];
    const float* bx = (const float*)d_in[2];
    const float* Wfx = (const float*)d_in[3];
    const float* bfx = (const float*)d_in[4];
    const float* Wsl = (const float*)d_in[5];
    const float* bsl = (const float*)d_in[6];
    const float* temp = (const float*)d_in[7];
    const float* Wqkv = (const float*)d_in[8];
    const float* Wout = (const float*)d_in[9];
    const float* bout = (const float*)d_in[10];
    float* out = (float*)d_out;

    const int SMEM = 98304 + 512;  // 3 stages x 32KB + bias
    cudaFuncSetAttribute(k1, cudaFuncAttributeMaxDynamicSharedMemorySize, SMEM);
    cudaFuncSetAttribute(k4, cudaFuncAttributeMaxDynamicSharedMemorySize, SMEM);
    const int SMEM2 = 5 * 14336;  // 71680
    cudaFuncSetAttribute(k2, cudaFuncAttributeMaxDynamicSharedMemorySize, SMEM2);

    k0<<<768, 256>>>(Wx, bx, Wfx, bfx, Wsl, bsl, temp);
    kprep<<<8192, 256>>>(x);
    k1<<<dim3(6, 512), 256, SMEM>>>();
    k2<<<dim3(64, 16), 256, SMEM2>>>();
    k3<<<16, 256>>>(Wqkv, Wout);
    k4<<<dim3(2, 512), 256, SMEM>>>(out, bout);
}